// round 2
// baseline (speedup 1.0000x reference)
#include <cuda_runtime.h>
#include <cuda_bf16.h>
#include <math_constants.h>

// VQ forward:
//   idx[n]   = argmin_j ||x_n - c_j||^2  == argmin_j (||c_j||^2 - 2 x_n . c_j)
//   out[n,:] = codebook[idx[n], :]              (straight-through => forward == gather)
//   loss     = 0.25 * mean((out - x)^2)         (appended after the quantized block)

#define DDIM 256
#define BM 128
#define BN 128
#define BK 32
#define TM 8
#define TN 8
#define NTHREADS 256
#define MAX_N 65536
#define MAX_K 16384
#define GATHER_BLOCKS 256

__device__ float g_cnorm[MAX_K];
__device__ int   g_idx[MAX_N];
__device__ float g_partial[GATHER_BLOCKS];

// ---------------------------------------------------------------------------
// Kernel 1: squared norms of codebook rows
// ---------------------------------------------------------------------------
__global__ void vq_norms(const float* __restrict__ cb, int K) {
    int j = blockIdx.x * blockDim.x + threadIdx.x;
    if (j < K) {
        const float4* r = reinterpret_cast<const float4*>(cb + (size_t)j * DDIM);
        float s = 0.f;
#pragma unroll
        for (int i = 0; i < DDIM / 4; i++) {
            float4 v = r[i];
            s += v.x * v.x + v.y * v.y + v.z * v.z + v.w * v.w;
        }
        g_cnorm[j] = s;
    }
}

// ---------------------------------------------------------------------------
// Kernel 2: fused (x . c^T) GEMM + row argmin. Score matrix never hits memory.
//   Block: 128 tokens. Loops over code chunks of 128, K-tiles of 32.
//   Each of 256 threads owns an 8x8 micro-tile; keeps running (min,idx) for
//   its 8 rows across ALL chunks; final cross-thread reduce with
//   lowest-index tie-break (jnp.argmin picks first occurrence == min index).
// ---------------------------------------------------------------------------
__global__ __launch_bounds__(NTHREADS, 2)
void vq_dist_argmin(const float* __restrict__ x, const float* __restrict__ cb,
                    int N, int K) {
    __shared__ __align__(16) float As[BK][BM + 4];   // k-major: As[k][m]
    __shared__ __align__(16) float Bs[BK][BN + 4];   // k-major: Bs[k][n]

    const int tid = threadIdx.x;
    const int tx = tid & 15;          // 16 column-threads
    const int ty = tid >> 4;          // 16 row-threads
    const int m0 = blockIdx.x * BM;

    float bestv[TM];
    int   besti[TM];
#pragma unroll
    for (int i = 0; i < TM; i++) { bestv[i] = CUDART_INF_F; besti[i] = 0; }

    for (int n0 = 0; n0 < K; n0 += BN) {
        float acc[TM][TN];
#pragma unroll
        for (int i = 0; i < TM; i++)
#pragma unroll
            for (int j = 0; j < TN; j++) acc[i][j] = 0.f;

        for (int k0 = 0; k0 < DDIM; k0 += BK) {
            // Load A tile (128 x 32) and B tile (128 x 32), transposed to k-major.
#pragma unroll
            for (int l = 0; l < 4; l++) {
                int s = tid + l * NTHREADS;      // 0..1023
                int row = s >> 3;                // 0..127
                int kv = s & 7;                  // float4 index along K
                float4 va = *reinterpret_cast<const float4*>(
                    x + (size_t)(m0 + row) * DDIM + k0 + kv * 4);
                As[kv * 4 + 0][row] = va.x;
                As[kv * 4 + 1][row] = va.y;
                As[kv * 4 + 2][row] = va.z;
                As[kv * 4 + 3][row] = va.w;
                float4 vb = *reinterpret_cast<const float4*>(
                    cb + (size_t)(n0 + row) * DDIM + k0 + kv * 4);
                Bs[kv * 4 + 0][row] = vb.x;
                Bs[kv * 4 + 1][row] = vb.y;
                Bs[kv * 4 + 2][row] = vb.z;
                Bs[kv * 4 + 3][row] = vb.w;
            }
            __syncthreads();

#pragma unroll
            for (int k = 0; k < BK; k++) {
                float a[TM], b[TN];
                *reinterpret_cast<float4*>(&a[0]) =
                    *reinterpret_cast<const float4*>(&As[k][ty * TM]);
                *reinterpret_cast<float4*>(&a[4]) =
                    *reinterpret_cast<const float4*>(&As[k][ty * TM + 4]);
                *reinterpret_cast<float4*>(&b[0]) =
                    *reinterpret_cast<const float4*>(&Bs[k][tx * TN]);
                *reinterpret_cast<float4*>(&b[4]) =
                    *reinterpret_cast<const float4*>(&Bs[k][tx * TN + 4]);
#pragma unroll
                for (int i = 0; i < TM; i++)
#pragma unroll
                    for (int j = 0; j < TN; j++)
                        acc[i][j] += a[i] * b[j];
            }
            __syncthreads();
        }

        // Fold this chunk's scores into the running argmin.
        float cn[TN];
#pragma unroll
        for (int j = 0; j < TN; j++) cn[j] = g_cnorm[n0 + tx * TN + j];
#pragma unroll
        for (int i = 0; i < TM; i++) {
#pragma unroll
            for (int j = 0; j < TN; j++) {         // ascending j -> earliest idx wins ties
                float s = fmaf(-2.f, acc[i][j], cn[j]);
                if (s < bestv[i]) { bestv[i] = s; besti[i] = n0 + tx * TN + j; }
            }
        }
    }

    // Cross-thread reduction over the 16 column-threads of each row.
    __syncthreads();
    float* sv = reinterpret_cast<float*>(&As[0][0]);   // [128][16]
    int*   si = reinterpret_cast<int*>(&Bs[0][0]);     // [128][16]
#pragma unroll
    for (int i = 0; i < TM; i++) {
        sv[(ty * TM + i) * 16 + tx] = bestv[i];
        si[(ty * TM + i) * 16 + tx] = besti[i];
    }
    __syncthreads();
    if (tid < BM) {
        int row = tid;
        float bv = sv[row * 16];
        int bi = si[row * 16];
#pragma unroll
        for (int t = 1; t < 16; t++) {
            float v = sv[row * 16 + t];
            int id = si[row * 16 + t];
            if (v < bv || (v == bv && id < bi)) { bv = v; bi = id; }
        }
        g_idx[m0 + row] = bi;
    }
}

// ---------------------------------------------------------------------------
// Kernel 3: gather quantized rows + per-block MSE partials (deterministic).
// ---------------------------------------------------------------------------
__global__ __launch_bounds__(256)
void vq_gather(const float* __restrict__ x, const float* __restrict__ cb,
               float* __restrict__ out, int nd4) {
    const int stride = gridDim.x * blockDim.x;
    float s = 0.f;
    for (int e = blockIdx.x * blockDim.x + threadIdx.x; e < nd4; e += stride) {
        int token = e >> 6;          // D/4 = 64 float4 per token
        int d4 = e & 63;
        int idx = g_idx[token];
        float4 c = *reinterpret_cast<const float4*>(cb + (size_t)idx * DDIM + d4 * 4);
        float4 xv = reinterpret_cast<const float4*>(x)[e];
        reinterpret_cast<float4*>(out)[e] = c;
        float dx = c.x - xv.x, dy = c.y - xv.y, dz = c.z - xv.z, dw = c.w - xv.w;
        s += dx * dx + dy * dy + dz * dz + dw * dw;
    }
    __shared__ float red[256];
    red[threadIdx.x] = s;
    __syncthreads();
    for (int off = 128; off > 0; off >>= 1) {
        if (threadIdx.x < off) red[threadIdx.x] += red[threadIdx.x + off];
        __syncthreads();
    }
    if (threadIdx.x == 0) g_partial[blockIdx.x] = red[0];
}

// ---------------------------------------------------------------------------
// Kernel 4: final loss reduction (fixed order -> deterministic), write tail.
// ---------------------------------------------------------------------------
__global__ void vq_finish(float* __restrict__ out, int nd, int out_size, int nblocks) {
    if (threadIdx.x == 0 && blockIdx.x == 0) {
        float s = 0.f;
        for (int i = 0; i < nblocks; i++) s += g_partial[i];
        float loss = 0.25f * s / (float)nd;
        for (int i = nd; i < out_size; i++) out[i] = loss;
    }
}

// ---------------------------------------------------------------------------
extern "C" void kernel_launch(void* const* d_in, const int* in_sizes, int n_in,
                              void* d_out, int out_size) {
    const float* x  = (const float*)d_in[0];
    const float* cb = (const float*)d_in[1];
    float* out = (float*)d_out;

    const int N = in_sizes[0] / DDIM;   // 32768 tokens
    const int K = in_sizes[1] / DDIM;   // 8192 codes
    const int nd = N * DDIM;

    vq_norms<<<(K + 255) / 256, 256>>>(cb, K);
    vq_dist_argmin<<<N / BM, NTHREADS>>>(x, cb, N, K);
    vq_gather<<<GATHER_BLOCKS, 256>>>(x, cb, out, nd / 4);
    vq_finish<<<1, 32>>>(out, nd, out_size, GATHER_BLOCKS);
}

// round 4
// speedup vs baseline: 3.6564x; 3.6564x over previous
#include <cuda_runtime.h>
#include <cuda_fp16.h>
#include <math_constants.h>
#include <cstdint>

// =============================================================================
// VQ forward, fp16 tensor cores (mma.sync, compute_103-safe):
//   approx score(n,j) = ||c_j||^2 - 2*(hi_x+lo_x).fp16(c_j)
//   per-thread top-3 candidates per row -> exact fp32 rescore within margin
// =============================================================================

#define DDIM 256
#define TILE_M 128          // tokens per CTA
#define TILE_N 128          // codes per n-chunk
#define NCHUNK_K 4          // 4 B-slices of 64 halves per n-chunk
#define MAX_N 65536
#define MAX_K 8192
#define GATHER_BLOCKS 256
#define MARGIN 0.5f

#define A_LO_OFF  65536
#define B_OFF    131072
#define B_STAGE   16384
#define SMEM_TOTAL (B_OFF + 2 * B_STAGE)    // 163840 B

__device__ float  g_cnorm[MAX_K];
__device__ int    g_idx[MAX_N];
__device__ float  g_partial[GATHER_BLOCKS];
__device__ __half g_cb_h[MAX_K * DDIM];

// ------------------------------------------------------------------ helpers
__device__ __forceinline__ uint32_t smem_u32(const void* p) {
    uint32_t a;
    asm("{ .reg .u64 t; cvta.to.shared.u64 t, %1; cvt.u32.u64 %0, t; }"
        : "=r"(a) : "l"(p));
    return a;
}
__device__ __forceinline__ void cp_async16(uint32_t dst, const void* src) {
    asm volatile("cp.async.cg.shared.global [%0], [%1], 16;"
                 :: "r"(dst), "l"(src) : "memory");
}
#define CP_COMMIT() asm volatile("cp.async.commit_group;" ::: "memory")
#define CP_WAIT1()  asm volatile("cp.async.wait_group 1;" ::: "memory")
#define CP_WAIT0()  asm volatile("cp.async.wait_group 0;" ::: "memory")

__device__ __forceinline__ void ldsm4(uint32_t& r0, uint32_t& r1, uint32_t& r2,
                                      uint32_t& r3, uint32_t addr) {
    asm volatile("ldmatrix.sync.aligned.m8n8.x4.shared.b16 {%0,%1,%2,%3}, [%4];"
                 : "=r"(r0), "=r"(r1), "=r"(r2), "=r"(r3) : "r"(addr));
}
__device__ __forceinline__ void mma16816(float* d, const uint32_t* a,
                                         uint32_t b0, uint32_t b1) {
    asm volatile(
        "mma.sync.aligned.m16n8k16.row.col.f32.f16.f16.f32 "
        "{%0,%1,%2,%3}, {%4,%5,%6,%7}, {%8,%9}, {%0,%1,%2,%3};"
        : "+f"(d[0]), "+f"(d[1]), "+f"(d[2]), "+f"(d[3])
        : "r"(a[0]), "r"(a[1]), "r"(a[2]), "r"(a[3]), "r"(b0), "r"(b1));
}
__device__ __forceinline__ uint32_t pack2(unsigned short a, unsigned short b) {
    return (uint32_t)a | ((uint32_t)b << 16);
}

// ---------------------------------------------------------------------------
// Kernel 1: codebook squared norms (fp32)
// ---------------------------------------------------------------------------
__global__ void vq_norms(const float* __restrict__ cb, int K) {
    int j = blockIdx.x * blockDim.x + threadIdx.x;
    if (j < K) {
        const float4* r = reinterpret_cast<const float4*>(cb + (size_t)j * DDIM);
        float s = 0.f;
#pragma unroll
        for (int i = 0; i < DDIM / 4; i++) {
            float4 v = r[i];
            s += v.x * v.x + v.y * v.y + v.z * v.z + v.w * v.w;
        }
        g_cnorm[j] = s;
    }
}

// ---------------------------------------------------------------------------
// Kernel 2: codebook fp32 -> fp16 (hi only)
// ---------------------------------------------------------------------------
__global__ void vq_cvt(const float* __restrict__ cb, int total4) {
    int i = blockIdx.x * blockDim.x + threadIdx.x;
    if (i < total4) {
        float4 v = reinterpret_cast<const float4*>(cb)[i];
        unsigned short h0 = __half_as_ushort(__float2half_rn(v.x));
        unsigned short h1 = __half_as_ushort(__float2half_rn(v.y));
        unsigned short h2 = __half_as_ushort(__float2half_rn(v.z));
        unsigned short h3 = __half_as_ushort(__float2half_rn(v.w));
        reinterpret_cast<uint2*>(g_cb_h)[i] = make_uint2(pack2(h0, h1), pack2(h2, h3));
    }
}

// ---------------------------------------------------------------------------
// Kernel 3: fused fp16 mma.sync GEMM + streaming argmin + exact rescore.
//   256 threads = 8 warps as 2(m) x 4(n); warp tile 64x32; BK slice = 64 halves.
//   A (hi|lo of x) resident in smem; B (fp16 codebook) double-buffered cp.async.
// ---------------------------------------------------------------------------
__global__ __launch_bounds__(256, 1)
void vq_gemm(const float* __restrict__ x, const float* __restrict__ cb, int K) {
    extern __shared__ __align__(1024) char smem[];
    const uint32_t sb = smem_u32(smem);
    const int tid = threadIdx.x;
    const int lane = tid & 31;
    const int warp = tid >> 5;
    const int warp_m = warp >> 2;          // 0..1
    const int warp_n = warp & 3;           // 0..3
    const int m0 = blockIdx.x * TILE_M;
    const int G = (K / TILE_N) * NCHUNK_K; // 256 B-slices

    // ---- A: load x rows, split fp32 -> fp16 hi + fp16 residual, swizzled ----
    for (int g = tid; g < TILE_M * 32; g += 256) {       // 16B granules
        int r = g >> 5, gk = g & 31;                     // row, granule (8 halves)
        const float4* src =
            reinterpret_cast<const float4*>(x + (size_t)(m0 + r) * DDIM + gk * 8);
        float4 v0 = src[0], v1 = src[1];
        float f[8] = {v0.x, v0.y, v0.z, v0.w, v1.x, v1.y, v1.z, v1.w};
        unsigned short hs[8], ls[8];
#pragma unroll
        for (int c = 0; c < 8; c++) {
            __half h = __float2half_rn(f[c]);
            float  res = f[c] - __half2float(h);
            hs[c] = __half_as_ushort(h);
            ls[c] = __half_as_ushort(__float2half_rn(res));
        }
        uint32_t off = r * 512 + (gk >> 3) * 128 + ((((gk ^ r) & 7)) << 4);
        *reinterpret_cast<uint4*>(smem + off) =
            make_uint4(pack2(hs[0], hs[1]), pack2(hs[2], hs[3]),
                       pack2(hs[4], hs[5]), pack2(hs[6], hs[7]));
        *reinterpret_cast<uint4*>(smem + A_LO_OFF + off) =
            make_uint4(pack2(ls[0], ls[1]), pack2(ls[2], ls[3]),
                       pack2(ls[4], ls[5]), pack2(ls[6], ls[7]));
    }

    // ---- per-lane ldmatrix address bases ----
    const int a_row = warp_m * 64 + (lane & 15);
    const int a_r7 = a_row & 7;
    uint32_t a_base[4];
#pragma unroll
    for (int mf = 0; mf < 4; mf++) a_base[mf] = sb + (a_row + mf * 16) * 512;
    // B: x4 covers 2 nfrags; n = warp_n*32 + p*16 + (lane&7) + ((lane>>4)<<3)
    const int b_nlo = (lane & 7) + ((lane >> 4) << 3);
    const int b_gbit = (lane >> 3) & 1;                  // k-half within k16
    uint32_t b_rowoff[2];
#pragma unroll
    for (int p = 0; p < 2; p++)
        b_rowoff[p] = (warp_n * 32 + p * 16 + b_nlo) * 128;

    float acc[4][4][4];
#pragma unroll
    for (int a1 = 0; a1 < 4; a1++)
#pragma unroll
        for (int a2 = 0; a2 < 4; a2++)
#pragma unroll
            for (int a3 = 0; a3 < 4; a3++) acc[a1][a2][a3] = 0.f;

    float tv0[8], tv1[8], tv2[8];
    int   ti0[8], ti1[8], ti2[8];
#pragma unroll
    for (int s = 0; s < 8; s++) {
        tv0[s] = tv1[s] = tv2[s] = CUDART_INF_F;
        ti0[s] = ti1[s] = ti2[s] = 0;
    }

    // ---- B slice producer (all 256 threads cooperate; 4 granules each) ----
    auto issueB = [&](int g) {
        int nc = g >> 2, kc = g & 3;
        const __half* gb = g_cb_h + (size_t)(nc * TILE_N) * DDIM + kc * 64;
        uint32_t bbuf = sb + B_OFF + (g & 1) * B_STAGE;
#pragma unroll
        for (int j = 0; j < 4; j++) {
            int lin = tid + j * 256;                 // 0..1023
            int n = lin >> 3, gk = lin & 7;
            cp_async16(bbuf + n * 128 + (((gk ^ n) & 7) << 4),
                       gb + (size_t)n * DDIM + gk * 8);
        }
        CP_COMMIT();
    };

    issueB(0);

    for (int g = 0; g < G; g++) {
        __syncthreads();                     // prior reads of buf[(g+1)&1] done
        if (g + 1 < G) { issueB(g + 1); CP_WAIT1(); }
        else           { CP_WAIT0(); }
        __syncthreads();                     // slice g visible to all

        const uint32_t bbuf = sb + B_OFF + (g & 1) * B_STAGE;
        const int kc = g & 3;
#pragma unroll
        for (int s = 0; s < 4; s++) {        // k16 steps within slice
            uint32_t br[8];
#pragma unroll
            for (int p = 0; p < 2; p++) {
                int gk = s * 2 + b_gbit;
                uint32_t addr = bbuf + b_rowoff[p] + (((gk ^ b_nlo) & 7) << 4);
                ldsm4(br[p * 4 + 0], br[p * 4 + 1], br[p * 4 + 2], br[p * 4 + 3], addr);
            }
            int kabs = kc * 4 + s;           // k16 index 0..15
            int ga = kabs * 2 + (lane >> 4);
            uint32_t aoff = (ga >> 3) * 128 + ((((ga & 7) ^ a_r7)) << 4);
#pragma unroll
            for (int mf = 0; mf < 4; mf++) { // A-hi
                uint32_t ar[4];
                ldsm4(ar[0], ar[1], ar[2], ar[3], a_base[mf] + aoff);
#pragma unroll
                for (int nf = 0; nf < 4; nf++)
                    mma16816(acc[mf][nf], ar, br[(nf >> 1) * 4 + (nf & 1) * 2],
                             br[(nf >> 1) * 4 + (nf & 1) * 2 + 1]);
            }
#pragma unroll
            for (int mf = 0; mf < 4; mf++) { // A-lo (same accumulators)
                uint32_t ar[4];
                ldsm4(ar[0], ar[1], ar[2], ar[3], a_base[mf] + A_LO_OFF + aoff);
#pragma unroll
                for (int nf = 0; nf < 4; nf++)
                    mma16816(acc[mf][nf], ar, br[(nf >> 1) * 4 + (nf & 1) * 2],
                             br[(nf >> 1) * 4 + (nf & 1) * 2 + 1]);
            }
        }

        if ((g & 3) == 3) {
            // ---- fold chunk scores into per-row top-3 ----
            int n_base = (g >> 2) * TILE_N + warp_n * 32 + (lane & 3) * 2;
#pragma unroll
            for (int nf = 0; nf < 4; nf++) {
                int ncol = n_base + nf * 8;
                float cn0 = __ldg(&g_cnorm[ncol]);
                float cn1 = __ldg(&g_cnorm[ncol + 1]);
#pragma unroll
                for (int mf = 0; mf < 4; mf++) {
#pragma unroll
                    for (int h = 0; h < 2; h++) {
                        int slot = mf * 2 + h;
                        float s0 = fmaf(-2.f, acc[mf][nf][h * 2 + 0], cn0);
                        float s1 = fmaf(-2.f, acc[mf][nf][h * 2 + 1], cn1);
#pragma unroll
                        for (int q = 0; q < 2; q++) {
                            float sv = q ? s1 : s0;
                            int   si = ncol + q;
                            if (sv < tv2[slot]) {
                                if (sv < tv1[slot]) {
                                    if (sv < tv0[slot]) {
                                        tv2[slot] = tv1[slot]; ti2[slot] = ti1[slot];
                                        tv1[slot] = tv0[slot]; ti1[slot] = ti0[slot];
                                        tv0[slot] = sv;        ti0[slot] = si;
                                    } else {
                                        tv2[slot] = tv1[slot]; ti2[slot] = ti1[slot];
                                        tv1[slot] = sv;        ti1[slot] = si;
                                    }
                                } else { tv2[slot] = sv; ti2[slot] = si; }
                            }
                        }
                        acc[mf][nf][h * 2 + 0] = 0.f;
                        acc[mf][nf][h * 2 + 1] = 0.f;
                    }
                }
            }
        }
    }

    // ---- cross-thread candidate collection (16 threads x 3 per row) ----
    __syncthreads();
    float* sv = reinterpret_cast<float*>(smem);             // [128][48]
    int*   si = reinterpret_cast<int*>(smem + 128 * 48 * 4);
    const int t16 = warp_n * 4 + (lane & 3);
#pragma unroll
    for (int slot = 0; slot < 8; slot++) {
        int row = warp_m * 64 + (slot >> 1) * 16 + (lane >> 2) + (slot & 1) * 8;
        int base = row * 48 + t16 * 3;
        sv[base + 0] = tv0[slot]; si[base + 0] = ti0[slot];
        sv[base + 1] = tv1[slot]; si[base + 1] = ti1[slot];
        sv[base + 2] = tv2[slot]; si[base + 2] = ti2[slot];
    }
    __syncthreads();

    if (tid < TILE_M) {
        int row = tid;
        float vmin = CUDART_INF_F;
#pragma unroll 8
        for (int j = 0; j < 48; j++) vmin = fminf(vmin, sv[row * 48 + j]);
        float thresh = vmin + MARGIN;

        const float4* xr = reinterpret_cast<const float4*>(x + (size_t)(m0 + row) * DDIM);
        float bs = CUDART_INF_F;
        int   bi = 0x7FFFFFFF;
        for (int j = 0; j < 48; j++) {
            if (sv[row * 48 + j] <= thresh) {
                int idx = si[row * 48 + j];
                const float4* cr = reinterpret_cast<const float4*>(cb + (size_t)idx * DDIM);
                float dot = 0.f;
#pragma unroll 16
                for (int k = 0; k < DDIM / 4; k++) {
                    float4 a = __ldg(&xr[k]);
                    float4 b = __ldg(&cr[k]);
                    dot += a.x * b.x + a.y * b.y + a.z * b.z + a.w * b.w;
                }
                float es = fmaf(-2.f, dot, __ldg(&g_cnorm[idx]));
                if (es < bs || (es == bs && idx < bi)) { bs = es; bi = idx; }
            }
        }
        g_idx[m0 + row] = bi;
    }
}

// ---------------------------------------------------------------------------
// Kernel 4: gather quantized rows + per-block MSE partials (deterministic)
// ---------------------------------------------------------------------------
__global__ __launch_bounds__(256)
void vq_gather(const float* __restrict__ x, const float* __restrict__ cb,
               float* __restrict__ out, int nd4) {
    const int stride = gridDim.x * blockDim.x;
    float s = 0.f;
    for (int e = blockIdx.x * blockDim.x + threadIdx.x; e < nd4; e += stride) {
        int token = e >> 6;
        int d4 = e & 63;
        int idx = g_idx[token];
        float4 c = *reinterpret_cast<const float4*>(cb + (size_t)idx * DDIM + d4 * 4);
        float4 xv = reinterpret_cast<const float4*>(x)[e];
        reinterpret_cast<float4*>(out)[e] = c;
        float dx = c.x - xv.x, dy = c.y - xv.y, dz = c.z - xv.z, dw = c.w - xv.w;
        s += dx * dx + dy * dy + dz * dz + dw * dw;
    }
    __shared__ float red[256];
    red[threadIdx.x] = s;
    __syncthreads();
    for (int off = 128; off > 0; off >>= 1) {
        if (threadIdx.x < off) red[threadIdx.x] += red[threadIdx.x + off];
        __syncthreads();
    }
    if (threadIdx.x == 0) g_partial[blockIdx.x] = red[0];
}

// ---------------------------------------------------------------------------
// Kernel 5: final loss reduction, broadcast into output tail
// ---------------------------------------------------------------------------
__global__ void vq_finish(float* __restrict__ out, int nd, int out_size, int nblocks) {
    if (threadIdx.x == 0 && blockIdx.x == 0) {
        float s = 0.f;
        for (int i = 0; i < nblocks; i++) s += g_partial[i];
        float loss = 0.25f * s / (float)nd;
        for (int i = nd; i < out_size; i++) out[i] = loss;
    }
}

// ---------------------------------------------------------------------------
extern "C" void kernel_launch(void* const* d_in, const int* in_sizes, int n_in,
                              void* d_out, int out_size) {
    const float* x  = (const float*)d_in[0];
    const float* cb = (const float*)d_in[1];
    float* out = (float*)d_out;

    const int N = in_sizes[0] / DDIM;   // 32768 tokens
    const int K = in_sizes[1] / DDIM;   // 8192 codes
    const int nd = N * DDIM;

    cudaFuncSetAttribute(vq_gemm, cudaFuncAttributeMaxDynamicSharedMemorySize,
                         SMEM_TOTAL);

    vq_norms<<<(K + 255) / 256, 256>>>(cb, K);
    vq_cvt<<<(K * (DDIM / 4) + 255) / 256, 256>>>(cb, K * (DDIM / 4));
    vq_gemm<<<N / TILE_M, 256, SMEM_TOTAL>>>(x, cb, K);
    vq_gather<<<GATHER_BLOCKS, 256>>>(x, cb, out, nd / 4);
    vq_finish<<<1, 32>>>(out, nd, out_size, GATHER_BLOCKS);
}

// round 5
// speedup vs baseline: 6.6958x; 1.8312x over previous
#include <cuda_runtime.h>
#include <cuda_fp16.h>
#include <math_constants.h>
#include <cstdint>

// =============================================================================
// VQ forward, fp16 mma.sync (compute_103-safe PTX):
//   approx score(n,j) = ||c_j||^2 - 2*fp16(x_n).fp16(c_j)   (single fp16 GEMM)
//   per-thread top-2 candidates per row -> exact fp32 rescore within margin
// =============================================================================

#define DDIM 256
#define TILE_M 128          // tokens per CTA
#define TILE_N 128          // codes per n-chunk
#define MAX_N 65536
#define MAX_K 8192
#define GATHER_BLOCKS 1184
#define MARGIN 1.0f

#define B_OFF     65536     // A tile: 128 rows x 512B = 64KB
#define B_STAGE   16384     // 128 codes x 64 halves x 2B
#define SMEM_TOTAL (B_OFF + 2 * B_STAGE)    // 98304 B -> 2 CTAs/SM

__device__ float  g_cnorm[MAX_K];
__device__ int    g_idx[MAX_N];
__device__ float  g_partial[GATHER_BLOCKS];
__device__ __half g_cb_h[MAX_K * DDIM];

// ------------------------------------------------------------------ helpers
__device__ __forceinline__ uint32_t smem_u32(const void* p) {
    uint32_t a;
    asm("{ .reg .u64 t; cvta.to.shared.u64 t, %1; cvt.u32.u64 %0, t; }"
        : "=r"(a) : "l"(p));
    return a;
}
__device__ __forceinline__ void cp_async16(uint32_t dst, const void* src) {
    asm volatile("cp.async.cg.shared.global [%0], [%1], 16;"
                 :: "r"(dst), "l"(src) : "memory");
}
#define CP_COMMIT() asm volatile("cp.async.commit_group;" ::: "memory")
#define CP_WAIT1()  asm volatile("cp.async.wait_group 1;" ::: "memory")
#define CP_WAIT0()  asm volatile("cp.async.wait_group 0;" ::: "memory")

__device__ __forceinline__ void ldsm4(uint32_t& r0, uint32_t& r1, uint32_t& r2,
                                      uint32_t& r3, uint32_t addr) {
    asm volatile("ldmatrix.sync.aligned.m8n8.x4.shared.b16 {%0,%1,%2,%3}, [%4];"
                 : "=r"(r0), "=r"(r1), "=r"(r2), "=r"(r3) : "r"(addr));
}
__device__ __forceinline__ void mma16816(float* d, const uint32_t* a,
                                         uint32_t b0, uint32_t b1) {
    asm volatile(
        "mma.sync.aligned.m16n8k16.row.col.f32.f16.f16.f32 "
        "{%0,%1,%2,%3}, {%4,%5,%6,%7}, {%8,%9}, {%0,%1,%2,%3};"
        : "+f"(d[0]), "+f"(d[1]), "+f"(d[2]), "+f"(d[3])
        : "r"(a[0]), "r"(a[1]), "r"(a[2]), "r"(a[3]), "r"(b0), "r"(b1));
}
__device__ __forceinline__ uint32_t pack2(unsigned short a, unsigned short b) {
    return (uint32_t)a | ((uint32_t)b << 16);
}

// ---------------------------------------------------------------------------
// Kernel 1: fused codebook norms + fp32->fp16 convert. One warp per code row.
// ---------------------------------------------------------------------------
__global__ __launch_bounds__(256)
void vq_prep(const float* __restrict__ cb, int K) {
    int row = blockIdx.x * 8 + (threadIdx.x >> 5);
    int lane = threadIdx.x & 31;
    if (row >= K) return;
    const float4* src = reinterpret_cast<const float4*>(cb + (size_t)row * DDIM);
    float4 v0 = src[lane * 2], v1 = src[lane * 2 + 1];
    float f[8] = {v0.x, v0.y, v0.z, v0.w, v1.x, v1.y, v1.z, v1.w};
    float s = 0.f;
    unsigned short h[8];
#pragma unroll
    for (int c = 0; c < 8; c++) {
        s += f[c] * f[c];
        h[c] = __half_as_ushort(__float2half_rn(f[c]));
    }
#pragma unroll
    for (int o = 16; o > 0; o >>= 1) s += __shfl_down_sync(0xFFFFFFFFu, s, o);
    if (lane == 0) g_cnorm[row] = s;
    reinterpret_cast<uint4*>(g_cb_h + (size_t)row * DDIM)[lane] =
        make_uint4(pack2(h[0], h[1]), pack2(h[2], h[3]),
                   pack2(h[4], h[5]), pack2(h[6], h[7]));
}

// ---------------------------------------------------------------------------
// Kernel 2: fused fp16 mma.sync GEMM + streaming argmin + exact rescore.
//   8 warps as 2(m) x 4(n); warp tile 64x32; K slice = 64 halves, dbl-buffered.
// ---------------------------------------------------------------------------
__global__ __launch_bounds__(256, 2)
void vq_gemm(const float* __restrict__ x, const float* __restrict__ cb, int K) {
    extern __shared__ __align__(1024) char smem[];
    const uint32_t sb = smem_u32(smem);
    const int tid = threadIdx.x;
    const int lane = tid & 31;
    const int warp = tid >> 5;
    const int warp_m = warp >> 2;          // 0..1
    const int warp_n = warp & 3;           // 0..3
    const int m0 = blockIdx.x * TILE_M;
    const int G = (K / TILE_N) * 4;        // 256 B-slices

    // ---- A: load x rows, convert to fp16, swizzled smem (64KB) ----
    for (int g = tid; g < TILE_M * 32; g += 256) {       // 16B granules
        int r = g >> 5, gk = g & 31;
        const float4* src =
            reinterpret_cast<const float4*>(x + (size_t)(m0 + r) * DDIM + gk * 8);
        float4 v0 = src[0], v1 = src[1];
        float f[8] = {v0.x, v0.y, v0.z, v0.w, v1.x, v1.y, v1.z, v1.w};
        unsigned short hs[8];
#pragma unroll
        for (int c = 0; c < 8; c++) hs[c] = __half_as_ushort(__float2half_rn(f[c]));
        uint32_t off = r * 512 + (gk >> 3) * 128 + ((((gk ^ r) & 7)) << 4);
        *reinterpret_cast<uint4*>(smem + off) =
            make_uint4(pack2(hs[0], hs[1]), pack2(hs[2], hs[3]),
                       pack2(hs[4], hs[5]), pack2(hs[6], hs[7]));
    }

    // ---- per-lane ldmatrix address bases ----
    const int a_row = warp_m * 64 + (lane & 15);
    const int a_r7 = a_row & 7;
    uint32_t a_base[4];
#pragma unroll
    for (int mf = 0; mf < 4; mf++) a_base[mf] = sb + (a_row + mf * 16) * 512;
    const int b_nlo = (lane & 7) + ((lane >> 4) << 3);
    const int b_gbit = (lane >> 3) & 1;
    uint32_t b_rowoff[2];
#pragma unroll
    for (int p = 0; p < 2; p++)
        b_rowoff[p] = (warp_n * 32 + p * 16 + b_nlo) * 128;

    float acc[4][4][4];
#pragma unroll
    for (int a1 = 0; a1 < 4; a1++)
#pragma unroll
        for (int a2 = 0; a2 < 4; a2++)
#pragma unroll
            for (int a3 = 0; a3 < 4; a3++) acc[a1][a2][a3] = 0.f;

    float tv0[8], tv1[8];
    int   ti0[8], ti1[8];
#pragma unroll
    for (int s = 0; s < 8; s++) {
        tv0[s] = tv1[s] = CUDART_INF_F;
        ti0[s] = ti1[s] = 0;
    }

    // ---- B slice producer (all 256 threads, 4 x 16B each) ----
    auto issueB = [&](int g) {
        int nc = g >> 2, kc = g & 3;
        const __half* gb = g_cb_h + (size_t)(nc * TILE_N) * DDIM + kc * 64;
        uint32_t bbuf = sb + B_OFF + (g & 1) * B_STAGE;
#pragma unroll
        for (int j = 0; j < 4; j++) {
            int lin = tid + j * 256;
            int n = lin >> 3, gk = lin & 7;
            cp_async16(bbuf + n * 128 + (((gk ^ n) & 7) << 4),
                       gb + (size_t)n * DDIM + gk * 8);
        }
        CP_COMMIT();
    };

    issueB(0);

    for (int g = 0; g < G; g++) {
        __syncthreads();
        if (g + 1 < G) { issueB(g + 1); CP_WAIT1(); }
        else           { CP_WAIT0(); }
        __syncthreads();

        const uint32_t bbuf = sb + B_OFF + (g & 1) * B_STAGE;
        const int kc = g & 3;
#pragma unroll
        for (int s = 0; s < 4; s++) {        // k16 steps within slice
            uint32_t br[8];
#pragma unroll
            for (int p = 0; p < 2; p++) {
                int gk = s * 2 + b_gbit;
                uint32_t addr = bbuf + b_rowoff[p] + (((gk ^ b_nlo) & 7) << 4);
                ldsm4(br[p * 4 + 0], br[p * 4 + 1], br[p * 4 + 2], br[p * 4 + 3], addr);
            }
            int kabs = kc * 4 + s;
            int ga = kabs * 2 + (lane >> 4);
            uint32_t aoff = (ga >> 3) * 128 + ((((ga & 7) ^ a_r7)) << 4);
#pragma unroll
            for (int mf = 0; mf < 4; mf++) {
                uint32_t ar[4];
                ldsm4(ar[0], ar[1], ar[2], ar[3], a_base[mf] + aoff);
#pragma unroll
                for (int nf = 0; nf < 4; nf++)
                    mma16816(acc[mf][nf], ar, br[(nf >> 1) * 4 + (nf & 1) * 2],
                             br[(nf >> 1) * 4 + (nf & 1) * 2 + 1]);
            }
        }

        if ((g & 3) == 3) {
            // ---- fold chunk scores into per-row top-2 ----
            int n_base = (g >> 2) * TILE_N + warp_n * 32 + (lane & 3) * 2;
#pragma unroll
            for (int nf = 0; nf < 4; nf++) {
                int ncol = n_base + nf * 8;
                float cn0 = __ldg(&g_cnorm[ncol]);
                float cn1 = __ldg(&g_cnorm[ncol + 1]);
#pragma unroll
                for (int mf = 0; mf < 4; mf++) {
#pragma unroll
                    for (int h = 0; h < 2; h++) {
                        int slot = mf * 2 + h;
                        float s0 = fmaf(-2.f, acc[mf][nf][h * 2 + 0], cn0);
                        float s1 = fmaf(-2.f, acc[mf][nf][h * 2 + 1], cn1);
#pragma unroll
                        for (int q = 0; q < 2; q++) {
                            float sv = q ? s1 : s0;
                            int   si = ncol + q;
                            if (sv < tv1[slot]) {
                                if (sv < tv0[slot]) {
                                    tv1[slot] = tv0[slot]; ti1[slot] = ti0[slot];
                                    tv0[slot] = sv;        ti0[slot] = si;
                                } else { tv1[slot] = sv; ti1[slot] = si; }
                            }
                        }
                        acc[mf][nf][h * 2 + 0] = 0.f;
                        acc[mf][nf][h * 2 + 1] = 0.f;
                    }
                }
            }
        }
    }

    // ---- candidate collection: 16 threads x 2 per row (32/row) ----
    __syncthreads();
    float* sv = reinterpret_cast<float*>(smem);             // [128][32]
    int*   si = reinterpret_cast<int*>(smem + 128 * 32 * 4);
    const int t16 = warp_n * 4 + (lane & 3);
#pragma unroll
    for (int slot = 0; slot < 8; slot++) {
        int row = warp_m * 64 + (slot >> 1) * 16 + (lane >> 2) + (slot & 1) * 8;
        int base = row * 32 + t16 * 2;
        sv[base + 0] = tv0[slot]; si[base + 0] = ti0[slot];
        sv[base + 1] = tv1[slot]; si[base + 1] = ti1[slot];
    }
    __syncthreads();

    if (tid < TILE_M) {
        int row = tid;
        float vmin = CUDART_INF_F;
#pragma unroll 8
        for (int j = 0; j < 32; j++) vmin = fminf(vmin, sv[row * 32 + j]);
        float thresh = vmin + MARGIN;

        const float4* xr = reinterpret_cast<const float4*>(x + (size_t)(m0 + row) * DDIM);
        float bs = CUDART_INF_F;
        int   bi = 0x7FFFFFFF;
        for (int j = 0; j < 32; j++) {
            if (sv[row * 32 + j] <= thresh) {
                int idx = si[row * 32 + j];
                const float4* cr = reinterpret_cast<const float4*>(cb + (size_t)idx * DDIM);
                float dot = 0.f;
#pragma unroll 16
                for (int k = 0; k < DDIM / 4; k++) {
                    float4 a = __ldg(&xr[k]);
                    float4 b = __ldg(&cr[k]);
                    dot += a.x * b.x + a.y * b.y + a.z * b.z + a.w * b.w;
                }
                float es = fmaf(-2.f, dot, __ldg(&g_cnorm[idx]));
                if (es < bs || (es == bs && idx < bi)) { bs = es; bi = idx; }
            }
        }
        g_idx[m0 + row] = bi;
    }
}

// ---------------------------------------------------------------------------
// Kernel 3: gather quantized rows + per-block MSE partials (deterministic)
// ---------------------------------------------------------------------------
__global__ __launch_bounds__(256)
void vq_gather(const float* __restrict__ x, const float* __restrict__ cb,
               float* __restrict__ out, int nd4) {
    const int stride = gridDim.x * blockDim.x;
    float s = 0.f;
    for (int e = blockIdx.x * blockDim.x + threadIdx.x; e < nd4; e += stride) {
        int token = e >> 6;
        int d4 = e & 63;
        int idx = g_idx[token];
        float4 c = *reinterpret_cast<const float4*>(cb + (size_t)idx * DDIM + d4 * 4);
        float4 xv = reinterpret_cast<const float4*>(x)[e];
        reinterpret_cast<float4*>(out)[e] = c;
        float dx = c.x - xv.x, dy = c.y - xv.y, dz = c.z - xv.z, dw = c.w - xv.w;
        s += dx * dx + dy * dy + dz * dz + dw * dw;
    }
    __shared__ float red[256];
    red[threadIdx.x] = s;
    __syncthreads();
    for (int off = 128; off > 0; off >>= 1) {
        if (threadIdx.x < off) red[threadIdx.x] += red[threadIdx.x + off];
        __syncthreads();
    }
    if (threadIdx.x == 0) g_partial[blockIdx.x] = red[0];
}

// ---------------------------------------------------------------------------
// Kernel 4: final loss reduction (parallel, deterministic), write tail
// ---------------------------------------------------------------------------
__global__ void vq_finish(float* __restrict__ out, int nd, int out_size, int nblocks) {
    __shared__ float red[256];
    float s = 0.f;
    for (int i = threadIdx.x; i < nblocks; i += 256) s += g_partial[i];
    red[threadIdx.x] = s;
    __syncthreads();
    for (int off = 128; off > 0; off >>= 1) {
        if (threadIdx.x < off) red[threadIdx.x] += red[threadIdx.x + off];
        __syncthreads();
    }
    float loss = 0.25f * red[0] / (float)nd;
    for (int i = nd + threadIdx.x; i < out_size; i += 256) out[i] = loss;
}

// ---------------------------------------------------------------------------
extern "C" void kernel_launch(void* const* d_in, const int* in_sizes, int n_in,
                              void* d_out, int out_size) {
    const float* x  = (const float*)d_in[0];
    const float* cb = (const float*)d_in[1];
    float* out = (float*)d_out;

    const int N = in_sizes[0] / DDIM;   // 32768 tokens
    const int K = in_sizes[1] / DDIM;   // 8192 codes
    const int nd = N * DDIM;

    cudaFuncSetAttribute(vq_gemm, cudaFuncAttributeMaxDynamicSharedMemorySize,
                         SMEM_TOTAL);

    vq_prep<<<(K + 7) / 8, 256>>>(cb, K);
    vq_gemm<<<N / TILE_M, 256, SMEM_TOTAL>>>(x, cb, K);
    vq_gather<<<GATHER_BLOCKS, 256>>>(x, cb, out, nd / 4);
    vq_finish<<<1, 256>>>(out, nd, out_size, GATHER_BLOCKS);
}